// round 1
// baseline (speedup 1.0000x reference)
#include <cuda_runtime.h>
#include <cuda_bf16.h>
#include <math.h>

// Problem constants
#define B_    8
#define DIN   1024
#define T_    2048
#define K_    8192
#define DCB   8
#define NT    (B_*T_)          // 16384 total time positions

// Output layout (flattened tuple, all float32):
// z_q_out [B,1024,T] | commit[B] | cb_loss[B] | indices[B,T] | z_e[B,8,T]
#define OUT_ZQ     0
#define OUT_COMMIT (B_*DIN*T_)                  // 16777216
#define OUT_CBL    (OUT_COMMIT + B_)            // 16777224
#define OUT_IDX    (OUT_CBL + B_)               // 16777232
#define OUT_ZE     (OUT_IDX + NT)               // 16793616

// Scratch (device globals; no allocation allowed)
__device__ float g_w_in[DCB*DIN];      // normalized in weights [c][d]
__device__ float g_w_out[DIN*DCB];     // normalized out weights [o][c]
__device__ float g_cbn[K_*DCB];        // normalized codebook
__device__ float g_sc[K_];             // sum(cbn^2) per code
__device__ float g_encn[NT*DCB];       // normalized encodings (row-major, 32B rows)
__device__ int   g_idx[NT];            // argmin indices
__device__ float g_losssum[B_];        // per-batch sum of (z_e - z_q)^2

// ---------------------------------------------------------------------------
// Kernel W: prep — normalize codebook, w_out, w_in; zero loss accumulators.
// grid: 34 blocks x 256 threads.
//   blocks 0..31  : codebook rows (8192)
//   block  32     : w_out rows (1024)
//   block  33     : w_in rows (8, warp-per-row reduce) + zero losses
// ---------------------------------------------------------------------------
__global__ void kprep(const float* __restrict__ in_v,
                      const float* __restrict__ in_g,
                      const float* __restrict__ out_v,
                      const float* __restrict__ out_g,
                      const float* __restrict__ codebook)
{
    int bid = blockIdx.x;
    int tid = threadIdx.x;

    if (bid < 32) {
        int row = bid * 256 + tid;             // 0..8191
        const float4* c4 = (const float4*)codebook + row * 2;
        float4 a = c4[0], b = c4[1];
        float ss = a.x*a.x + a.y*a.y + a.z*a.z + a.w*a.w
                 + b.x*b.x + b.y*b.y + b.z*b.z + b.w*b.w;
        float nm = fmaxf(sqrtf(ss), 1e-12f);
        float inv = 1.0f / nm;
        float4 na = make_float4(a.x*inv, a.y*inv, a.z*inv, a.w*inv);
        float4 nb = make_float4(b.x*inv, b.y*inv, b.z*inv, b.w*inv);
        float4* o4 = (float4*)g_cbn + row * 2;
        o4[0] = na; o4[1] = nb;
        g_sc[row] = na.x*na.x + na.y*na.y + na.z*na.z + na.w*na.w
                  + nb.x*nb.x + nb.y*nb.y + nb.z*nb.z + nb.w*nb.w;
    } else if (bid == 32) {
        // w_out: 1024 rows of 8; w = g[o]*v[o,:]/||v[o,:]||  (no eps in _wn)
        for (int o = tid; o < DIN; o += 256) {
            const float4* v4 = (const float4*)out_v + o * 2;
            float4 a = v4[0], b = v4[1];
            float ss = a.x*a.x + a.y*a.y + a.z*a.z + a.w*a.w
                     + b.x*b.x + b.y*b.y + b.z*b.z + b.w*b.w;
            float s = out_g[o] / sqrtf(ss);
            float4* w4 = (float4*)g_w_out + o * 2;
            w4[0] = make_float4(a.x*s, a.y*s, a.z*s, a.w*s);
            w4[1] = make_float4(b.x*s, b.y*s, b.z*s, b.w*s);
        }
    } else {
        // w_in: 8 rows of 1024; warp w reduces row w
        __shared__ float norms[DCB];
        int w = tid >> 5, l = tid & 31;
        if (w < DCB) {
            float ss = 0.f;
            const float* vr = in_v + w * DIN;
            for (int j = l; j < DIN; j += 32) { float x = vr[j]; ss = fmaf(x, x, ss); }
            #pragma unroll
            for (int off = 16; off; off >>= 1)
                ss += __shfl_xor_sync(0xffffffffu, ss, off);
            if (l == 0) norms[w] = sqrtf(ss);
        }
        __syncthreads();
        for (int flat = tid; flat < DCB*DIN; flat += 256) {
            int c = flat >> 10;   // /1024
            g_w_in[flat] = in_g[c] * in_v[flat] / norms[c];
        }
        if (tid < B_) g_losssum[tid] = 0.f;
    }
}

// ---------------------------------------------------------------------------
// Kernel A: z_e = w_in @ z + b ; write z_e output and normalized enc to scratch.
// grid (T/64, B), 64 threads; smem holds full w_in (32KB).
// ---------------------------------------------------------------------------
__global__ void kinproj(const float* __restrict__ z,
                        const float* __restrict__ in_b,
                        float* __restrict__ out)
{
    __shared__ float ws[DCB*DIN];   // [c][d]
    int tid = threadIdx.x;
    // cooperative load: 2048 float4 / 64 threads = 32 each
    {
        const float4* s4 = (const float4*)g_w_in;
        float4* d4 = (float4*)ws;
        for (int j = tid; j < (DCB*DIN)/4; j += 64) d4[j] = s4[j];
    }
    __syncthreads();

    int t = blockIdx.x * 64 + tid;
    int b = blockIdx.y;
    const float* zp = z + (size_t)b * DIN * T_ + t;

    float acc[DCB];
    #pragma unroll
    for (int c = 0; c < DCB; c++) acc[c] = 0.f;

    #pragma unroll 4
    for (int d = 0; d < DIN; d++) {
        float zv = zp[(size_t)d * T_];
        #pragma unroll
        for (int c = 0; c < DCB; c++)
            acc[c] = fmaf(ws[c*DIN + d], zv, acc[c]);
    }

    float ze[DCB];
    float ss = 0.f;
    #pragma unroll
    for (int c = 0; c < DCB; c++) {
        ze[c] = acc[c] + in_b[c];
        ss = fmaf(ze[c], ze[c], ss);
    }
    // write z_e output
    float* oz = out + OUT_ZE + (size_t)b * DCB * T_ + t;
    #pragma unroll
    for (int c = 0; c < DCB; c++) oz[(size_t)c * T_] = ze[c];

    float inv = 1.0f / fmaxf(sqrtf(ss), 1e-12f);
    float4 e0 = make_float4(ze[0]*inv, ze[1]*inv, ze[2]*inv, ze[3]*inv);
    float4 e1 = make_float4(ze[4]*inv, ze[5]*inv, ze[6]*inv, ze[7]*inv);
    float4* en4 = (float4*)g_encn + (size_t)(b * T_ + t) * 2;
    en4[0] = e0; en4[1] = e1;
}

// ---------------------------------------------------------------------------
// Kernel B: argmin over codebook. 8 threads per time position, residue-
// interleaved over k (lane r scans k ≡ r mod 8) -> conflict-free broadcast LDS.
// grid 512 blocks (32 t each), 256 threads. SMEM tile: 1024 codes (36KB).
// Also computes per-batch loss sums and writes indices.
// ---------------------------------------------------------------------------
#define TILE_K 1024
__global__ void kargmin(const float* __restrict__ codebook,
                        float* __restrict__ out)
{
    __shared__ float cbs[TILE_K * DCB];
    __shared__ float scs[TILE_K];
    __shared__ float sloss;

    int tid = threadIdx.x;
    int r = tid & 7;
    int tg = blockIdx.x * 32 + (tid >> 3);   // global time position 0..16383
    int b = tg >> 11;                        // /2048
    int tt = tg & 2047;

    if (tid == 0) sloss = 0.f;

    // load encoding (all 8 lanes of a group load the same row; L1 broadcast)
    const float4* e4 = (const float4*)g_encn + (size_t)tg * 2;
    float4 ea = e4[0], eb = e4[1];
    float se = ((((((ea.x*ea.x + ea.y*ea.y) + ea.z*ea.z) + ea.w*ea.w)
               + eb.x*eb.x) + eb.y*eb.y + eb.z*eb.z) + eb.w*eb.w);

    float best = 3.4e38f;
    int   bi   = 0;

    const float4* cbs4 = (const float4*)cbs;

    for (int kb = 0; kb < K_; kb += TILE_K) {
        __syncthreads();
        // cooperative tile load
        {
            const float4* g4 = (const float4*)g_cbn + (size_t)kb * 2;
            float4* d4 = (float4*)cbs;
            #pragma unroll
            for (int j = tid; j < TILE_K*DCB/4; j += 256) d4[j] = g4[j];
            const float4* s4 = (const float4*)(g_sc + kb);
            ((float4*)scs)[tid] = s4[tid];   // 256 float4 = 1024 floats
        }
        __syncthreads();

        #pragma unroll 4
        for (int i = 0; i < TILE_K/8; i++) {
            int kl = i*8 + r;
            float4 c0 = cbs4[kl*2];
            float4 c1 = cbs4[kl*2 + 1];
            float da = ea.x*c0.x;
            da = fmaf(ea.y, c0.y, da);
            da = fmaf(ea.z, c0.z, da);
            da = fmaf(ea.w, c0.w, da);
            float db = eb.x*c1.x;
            db = fmaf(eb.y, c1.y, db);
            db = fmaf(eb.z, c1.z, db);
            db = fmaf(eb.w, c1.w, db);
            float dot = da + db;
            float dist = fmaf(-2.0f, dot, se) + scs[kl];
            if (dist < best) { best = dist; bi = kb + kl; }
        }
    }

    // reduce across the 8 lanes of the group (keep lowest index on tie)
    #pragma unroll
    for (int off = 4; off; off >>= 1) {
        float od = __shfl_xor_sync(0xffffffffu, best, off);
        int   oi = __shfl_xor_sync(0xffffffffu, bi,   off);
        if (od < best || (od == best && oi < bi)) { best = od; bi = oi; }
    }

    if (r == 0) {
        g_idx[tg] = bi;
        out[OUT_IDX + tg] = (float)bi;
    }

    // loss: each of the 8 lanes handles one dim
    float zer = out[OUT_ZE + ((size_t)b * DCB + r) * T_ + tt];
    float zqr = codebook[bi * DCB + r];
    float d = zer - zqr;
    float s = d * d;
    #pragma unroll
    for (int off = 4; off; off >>= 1)
        s += __shfl_xor_sync(0xffffffffu, s, off);
    if (r == 0) atomicAdd(&sloss, s);

    __syncthreads();
    if (tid == 0) atomicAdd(&g_losssum[b], sloss);
}

// ---------------------------------------------------------------------------
// Kernel C: out-projection. z_q_out = w_out @ z_q_st + out_b.
// grid (T/128, B, 2 o-halves), 128 threads.
// ---------------------------------------------------------------------------
__global__ void koutproj(const float* __restrict__ codebook,
                         const float* __restrict__ out_b,
                         float* __restrict__ out)
{
    __shared__ float ws[512 * DCB];   // 16KB: this block's o-slice of w_out
    __shared__ float obs[512];

    int tid = threadIdx.x;
    int t = blockIdx.x * 128 + tid;
    int b = blockIdx.y;
    int obase = blockIdx.z * 512;

    // cooperative loads
    {
        const float4* s4 = (const float4*)(g_w_out + obase * DCB);
        float4* d4 = (float4*)ws;
        #pragma unroll
        for (int j = tid; j < 512*DCB/4; j += 128) d4[j] = s4[j];
        ((float4*)obs)[tid] = ((const float4*)(out_b + obase))[tid];
    }

    // gather this thread's codeword + z_e, form straight-through value
    int ki = g_idx[b * T_ + t];
    const float4* q4 = (const float4*)codebook + ki * 2;
    float4 qa = q4[0], qb = q4[1];
    float zq[DCB] = {qa.x, qa.y, qa.z, qa.w, qb.x, qb.y, qb.z, qb.w};
    float zst[DCB];
    #pragma unroll
    for (int c = 0; c < DCB; c++) {
        float ze = out[OUT_ZE + ((size_t)b * DCB + c) * T_ + t];
        zst[c] = ze + (zq[c] - ze);   // forward value of straight-through
    }
    __syncthreads();

    const float4* ws4 = (const float4*)ws;
    float* op = out + OUT_ZQ + ((size_t)b * DIN + obase) * T_ + t;

    #pragma unroll 2
    for (int ol = 0; ol < 512; ol++) {
        float4 w0 = ws4[ol*2];
        float4 w1 = ws4[ol*2 + 1];
        float acc = w0.x * zst[0];
        acc = fmaf(w0.y, zst[1], acc);
        acc = fmaf(w0.z, zst[2], acc);
        acc = fmaf(w0.w, zst[3], acc);
        acc = fmaf(w1.x, zst[4], acc);
        acc = fmaf(w1.y, zst[5], acc);
        acc = fmaf(w1.z, zst[6], acc);
        acc = fmaf(w1.w, zst[7], acc);
        acc += obs[ol];
        op[(size_t)ol * T_] = acc;
    }
}

// ---------------------------------------------------------------------------
// Kernel D: finalize losses.
// ---------------------------------------------------------------------------
__global__ void kloss(float* __restrict__ out)
{
    int b = threadIdx.x;
    if (b < B_) {
        float m = g_losssum[b] / (float)(DCB * T_);
        out[OUT_COMMIT + b] = m * 0.005f;
        out[OUT_CBL + b]    = m * 1.0f;
    }
}

// ---------------------------------------------------------------------------
extern "C" void kernel_launch(void* const* d_in, const int* in_sizes, int n_in,
                              void* d_out, int out_size)
{
    const float* z        = (const float*)d_in[0];
    const float* in_v     = (const float*)d_in[1];
    const float* in_g     = (const float*)d_in[2];
    const float* in_b     = (const float*)d_in[3];
    const float* out_v    = (const float*)d_in[4];
    const float* out_g    = (const float*)d_in[5];
    const float* out_b    = (const float*)d_in[6];
    const float* codebook = (const float*)d_in[7];
    float* out = (float*)d_out;

    kprep<<<34, 256>>>(in_v, in_g, out_v, out_g, codebook);
    kinproj<<<dim3(T_/64, B_), 64>>>(z, in_b, out);
    kargmin<<<NT/32, 256>>>(codebook, out);
    koutproj<<<dim3(T_/128, B_, 2), 128>>>(codebook, out_b, out);
    kloss<<<1, 32>>>(out);
}

// round 2
// speedup vs baseline: 3.0665x; 3.0665x over previous
#include <cuda_runtime.h>
#include <cuda_bf16.h>
#include <math.h>

// Problem constants
#define B_    8
#define DIN   1024
#define T_    2048
#define K_    8192
#define DCB   8
#define NT    (B_*T_)          // 16384 total time positions
#define DSPLIT 16
#define DCHUNK (DIN/DSPLIT)    // 64

// Output layout (flattened tuple, all float32):
// z_q_out [B,1024,T] | commit[B] | cb_loss[B] | indices[B,T] | z_e[B,8,T]
#define OUT_ZQ     0
#define OUT_COMMIT (B_*DIN*T_)
#define OUT_CBL    (OUT_COMMIT + B_)
#define OUT_IDX    (OUT_CBL + B_)
#define OUT_ZE     (OUT_IDX + NT)

// Scratch (device globals; no allocation allowed)
__device__ float g_w_in[DCB*DIN];          // normalized in weights [c][d]
__device__ float g_w_out[DIN*DCB];         // normalized out weights [o][c]
__device__ __align__(16) float g_cbn[K_*DCB];   // normalized codebook
__device__ float g_sc[K_];                 // sum(cbn^2) per code
__device__ __align__(16) float g_encn[NT*DCB];  // normalized encodings
__device__ __align__(16) float g_part[DSPLIT*NT*DCB]; // split-K partials (8MB)
__device__ int   g_idx[NT];                // argmin indices
__device__ float g_losssum[B_];            // per-batch sum of (z_e - z_q)^2

// ---- packed f32x2 helpers ----
__device__ __forceinline__ unsigned long long fma2(unsigned long long a,
                                                   unsigned long long b,
                                                   unsigned long long c) {
    unsigned long long d;
    asm("fma.rn.f32x2 %0, %1, %2, %3;" : "=l"(d) : "l"(a), "l"(b), "l"(c));
    return d;
}
__device__ __forceinline__ unsigned long long mul2(unsigned long long a,
                                                   unsigned long long b) {
    unsigned long long d;
    asm("mul.rn.f32x2 %0, %1, %2;" : "=l"(d) : "l"(a), "l"(b));
    return d;
}
__device__ __forceinline__ void unpk2(unsigned long long p, float& lo, float& hi) {
    asm("mov.b64 {%0, %1}, %2;" : "=f"(lo), "=f"(hi) : "l"(p));
}

// ---------------------------------------------------------------------------
// Kernel W: prep — normalize codebook, w_out, w_in; zero loss accumulators.
// ---------------------------------------------------------------------------
__global__ void kprep(const float* __restrict__ in_v,
                      const float* __restrict__ in_g,
                      const float* __restrict__ out_v,
                      const float* __restrict__ out_g,
                      const float* __restrict__ codebook)
{
    int bid = blockIdx.x;
    int tid = threadIdx.x;

    if (bid < 32) {
        int row = bid * 256 + tid;             // 0..8191
        const float4* c4 = (const float4*)codebook + row * 2;
        float4 a = c4[0], b = c4[1];
        float ss = a.x*a.x + a.y*a.y + a.z*a.z + a.w*a.w
                 + b.x*b.x + b.y*b.y + b.z*b.z + b.w*b.w;
        float nm = fmaxf(sqrtf(ss), 1e-12f);
        float inv = 1.0f / nm;
        float4 na = make_float4(a.x*inv, a.y*inv, a.z*inv, a.w*inv);
        float4 nb = make_float4(b.x*inv, b.y*inv, b.z*inv, b.w*inv);
        float4* o4 = (float4*)g_cbn + row * 2;
        o4[0] = na; o4[1] = nb;
        g_sc[row] = na.x*na.x + na.y*na.y + na.z*na.z + na.w*na.w
                  + nb.x*nb.x + nb.y*nb.y + nb.z*nb.z + nb.w*nb.w;
    } else if (bid == 32) {
        for (int o = tid; o < DIN; o += 256) {
            const float4* v4 = (const float4*)out_v + o * 2;
            float4 a = v4[0], b = v4[1];
            float ss = a.x*a.x + a.y*a.y + a.z*a.z + a.w*a.w
                     + b.x*b.x + b.y*b.y + b.z*b.z + b.w*b.w;
            float s = out_g[o] / sqrtf(ss);
            float4* w4 = (float4*)g_w_out + o * 2;
            w4[0] = make_float4(a.x*s, a.y*s, a.z*s, a.w*s);
            w4[1] = make_float4(b.x*s, b.y*s, b.z*s, b.w*s);
        }
    } else {
        __shared__ float norms[DCB];
        int w = tid >> 5, l = tid & 31;
        if (w < DCB) {
            float ss = 0.f;
            const float* vr = in_v + w * DIN;
            for (int j = l; j < DIN; j += 32) { float x = vr[j]; ss = fmaf(x, x, ss); }
            #pragma unroll
            for (int off = 16; off; off >>= 1)
                ss += __shfl_xor_sync(0xffffffffu, ss, off);
            if (l == 0) norms[w] = sqrtf(ss);
        }
        __syncthreads();
        for (int flat = tid; flat < DCB*DIN; flat += 256) {
            int c = flat >> 10;
            g_w_in[flat] = in_g[c] * in_v[flat] / norms[c];
        }
        if (tid < B_) g_losssum[tid] = 0.f;
    }
}

// ---------------------------------------------------------------------------
// Kernel A1: split-K in-projection partials.
// grid (T/128, B, DSPLIT), 128 threads. Each thread: one t, one 64-d chunk.
// ---------------------------------------------------------------------------
__global__ void kinproj(const float* __restrict__ z)
{
    __shared__ __align__(16) float wst[DCHUNK * DCB];   // transposed [j][c], 2KB
    int tid = threadIdx.x;
    int ds  = blockIdx.z;

    for (int e = tid; e < DCHUNK*DCB; e += 128) {
        int c = e >> 6;            // /DCHUNK
        int j = e & (DCHUNK-1);
        wst[j*DCB + c] = g_w_in[c*DIN + ds*DCHUNK + j];
    }
    __syncthreads();

    int t = blockIdx.x * 128 + tid;
    int b = blockIdx.y;
    const float* zp = z + ((size_t)b * DIN + ds * DCHUNK) * T_ + t;

    float acc[DCB];
    #pragma unroll
    for (int c = 0; c < DCB; c++) acc[c] = 0.f;

    const float4* w4 = (const float4*)wst;
    #pragma unroll 8
    for (int j = 0; j < DCHUNK; j++) {
        float zv = zp[(size_t)j * T_];
        float4 w0 = w4[j*2];
        float4 w1 = w4[j*2 + 1];
        acc[0] = fmaf(w0.x, zv, acc[0]);
        acc[1] = fmaf(w0.y, zv, acc[1]);
        acc[2] = fmaf(w0.z, zv, acc[2]);
        acc[3] = fmaf(w0.w, zv, acc[3]);
        acc[4] = fmaf(w1.x, zv, acc[4]);
        acc[5] = fmaf(w1.y, zv, acc[5]);
        acc[6] = fmaf(w1.z, zv, acc[6]);
        acc[7] = fmaf(w1.w, zv, acc[7]);
    }

    int tg = b * T_ + t;
    float4* p4 = (float4*)(g_part + ((size_t)ds * NT + tg) * DCB);
    p4[0] = make_float4(acc[0], acc[1], acc[2], acc[3]);
    p4[1] = make_float4(acc[4], acc[5], acc[6], acc[7]);
}

// ---------------------------------------------------------------------------
// Kernel A2: combine partials (fixed order), add bias, write z_e, normalize.
// grid 64 x 256 threads, one thread per time position.
// ---------------------------------------------------------------------------
__global__ void kcombine(const float* __restrict__ in_b,
                         float* __restrict__ out)
{
    int tg = blockIdx.x * 256 + threadIdx.x;
    int b = tg >> 11;
    int t = tg & (T_-1);

    float4 a0 = make_float4(0,0,0,0), a1 = make_float4(0,0,0,0);
    #pragma unroll
    for (int ds = 0; ds < DSPLIT; ds++) {
        const float4* p4 = (const float4*)(g_part + ((size_t)ds * NT + tg) * DCB);
        float4 q0 = p4[0], q1 = p4[1];
        a0.x += q0.x; a0.y += q0.y; a0.z += q0.z; a0.w += q0.w;
        a1.x += q1.x; a1.y += q1.y; a1.z += q1.z; a1.w += q1.w;
    }
    float ze[DCB] = { a0.x + in_b[0], a0.y + in_b[1], a0.z + in_b[2], a0.w + in_b[3],
                      a1.x + in_b[4], a1.y + in_b[5], a1.z + in_b[6], a1.w + in_b[7] };

    float* oz = out + OUT_ZE + (size_t)b * DCB * T_ + t;
    float ss = 0.f;
    #pragma unroll
    for (int c = 0; c < DCB; c++) {
        oz[(size_t)c * T_] = ze[c];
        ss = fmaf(ze[c], ze[c], ss);
    }
    float inv = 1.0f / fmaxf(sqrtf(ss), 1e-12f);
    float4* en4 = (float4*)g_encn + (size_t)tg * 2;
    en4[0] = make_float4(ze[0]*inv, ze[1]*inv, ze[2]*inv, ze[3]*inv);
    en4[1] = make_float4(ze[4]*inv, ze[5]*inv, ze[6]*inv, ze[7]*inv);
}

// ---------------------------------------------------------------------------
// Kernel B: argmin. 8 lanes per group, Q=4 queries per group, packed f32x2.
// grid 128 blocks x 256 threads; each block = 128 queries (single batch).
// ---------------------------------------------------------------------------
#define TILE_K 1024
#define QB 4
__global__ void __launch_bounds__(256) kargmin(const float* __restrict__ codebook,
                                               float* __restrict__ out)
{
    __shared__ __align__(16) float cbs[TILE_K * DCB];   // 32KB
    __shared__ __align__(16) float scs[TILE_K];         // 4KB
    __shared__ float sloss;

    int tid = threadIdx.x;
    int r = tid & 7;
    int g = tid >> 3;                           // group 0..31
    int q0 = blockIdx.x * 128 + g * QB;         // first query of this group
    int b = q0 >> 11;                           // block fully inside one batch

    if (tid == 0) sloss = 0.f;

    // load 4 query encodings as packed f32x2
    unsigned long long e01[QB], e23[QB], e45[QB], e67[QB];
    float se[QB];
    #pragma unroll
    for (int q = 0; q < QB; q++) {
        const ulonglong2* e2 = (const ulonglong2*)g_encn + (size_t)(q0 + q) * 2;
        ulonglong2 A = e2[0], Bv = e2[1];
        e01[q] = A.x; e23[q] = A.y; e45[q] = Bv.x; e67[q] = Bv.y;
        unsigned long long p = fma2(A.x, A.x, fma2(A.y, A.y,
                                  fma2(Bv.x, Bv.x, mul2(Bv.y, Bv.y))));
        float lo, hi; unpk2(p, lo, hi);
        se[q] = lo + hi;
    }

    float best[QB]; int bi[QB];
    #pragma unroll
    for (int q = 0; q < QB; q++) { best[q] = 3.4e38f; bi[q] = 0; }

    const ulonglong2* c2 = (const ulonglong2*)cbs;

    for (int kb = 0; kb < K_; kb += TILE_K) {
        __syncthreads();
        {
            const float4* g4 = (const float4*)g_cbn + (size_t)kb * 2;
            float4* d4 = (float4*)cbs;
            #pragma unroll
            for (int j = tid; j < TILE_K*DCB/4; j += 256) d4[j] = g4[j];
            ((float4*)scs)[tid] = ((const float4*)(g_sc + kb))[tid];
        }
        __syncthreads();

        #pragma unroll 4
        for (int i = 0; i < TILE_K/8; i++) {
            int kl = i*8 + r;
            ulonglong2 ca = c2[kl*2];
            ulonglong2 cb = c2[kl*2 + 1];
            float sck = scs[kl];
            #pragma unroll
            for (int q = 0; q < QB; q++) {
                unsigned long long p = fma2(e01[q], ca.x, fma2(e23[q], ca.y,
                                         fma2(e45[q], cb.x, mul2(e67[q], cb.y))));
                float lo, hi; unpk2(p, lo, hi);
                float dist = fmaf(-2.0f, lo + hi, se[q]) + sck;
                if (dist < best[q]) { best[q] = dist; bi[q] = kb + kl; }
            }
        }
    }

    // reduce across the 8 lanes (keep lowest index on tie); butterfly leaves
    // all 8 lanes with the final value.
    #pragma unroll
    for (int q = 0; q < QB; q++) {
        #pragma unroll
        for (int off = 4; off; off >>= 1) {
            float od = __shfl_xor_sync(0xffffffffu, best[q], off);
            int   oi = __shfl_xor_sync(0xffffffffu, bi[q],   off);
            if (od < best[q] || (od == best[q] && oi < bi[q])) { best[q] = od; bi[q] = oi; }
        }
    }

    if (r == 0) {
        #pragma unroll
        for (int q = 0; q < QB; q++) {
            g_idx[q0 + q] = bi[q];
            out[OUT_IDX + q0 + q] = (float)bi[q];
        }
    }

    // loss: lane r handles dim r for each of the 4 queries
    float s = 0.f;
    #pragma unroll
    for (int q = 0; q < QB; q++) {
        int tq = q0 + q;
        int tt = tq & (T_-1);
        float ze = out[OUT_ZE + ((size_t)b * DCB + r) * T_ + tt];
        float zq = codebook[bi[q] * DCB + r];
        float d = ze - zq;
        s = fmaf(d, d, s);
    }
    #pragma unroll
    for (int off = 4; off; off >>= 1)
        s += __shfl_xor_sync(0xffffffffu, s, off);
    if (r == 0) atomicAdd(&sloss, s);

    __syncthreads();
    if (tid == 0) atomicAdd(&g_losssum[b], sloss);
}

// ---------------------------------------------------------------------------
// Kernel C: out-projection, o split into 8 chunks of 128.
// grid (T/128, B, 8), 128 threads.
// ---------------------------------------------------------------------------
#define OCH 128
__global__ void koutproj(const float* __restrict__ codebook,
                         const float* __restrict__ out_b,
                         float* __restrict__ out)
{
    __shared__ __align__(16) float ws[OCH * DCB];   // 4KB
    __shared__ float obs[OCH];

    int tid = threadIdx.x;
    int t = blockIdx.x * 128 + tid;
    int b = blockIdx.y;
    int obase = blockIdx.z * OCH;

    {
        const float4* s4 = (const float4*)(g_w_out + obase * DCB);
        float4* d4 = (float4*)ws;
        #pragma unroll
        for (int j = tid; j < OCH*DCB/4; j += 128) d4[j] = s4[j];
        if (tid < OCH) obs[tid] = out_b[obase + tid];
    }

    int ki = g_idx[b * T_ + t];
    const float4* q4 = (const float4*)codebook + ki * 2;
    float4 qa = q4[0], qb = q4[1];
    float zq[DCB] = {qa.x, qa.y, qa.z, qa.w, qb.x, qb.y, qb.z, qb.w};
    float zst[DCB];
    #pragma unroll
    for (int c = 0; c < DCB; c++) {
        float ze = out[OUT_ZE + ((size_t)b * DCB + c) * T_ + t];
        zst[c] = ze + (zq[c] - ze);   // straight-through forward value
    }
    __syncthreads();

    const float4* ws4 = (const float4*)ws;
    float* op = out + OUT_ZQ + ((size_t)b * DIN + obase) * T_ + t;

    #pragma unroll 4
    for (int ol = 0; ol < OCH; ol++) {
        float4 w0 = ws4[ol*2];
        float4 w1 = ws4[ol*2 + 1];
        float acc = w0.x * zst[0];
        acc = fmaf(w0.y, zst[1], acc);
        acc = fmaf(w0.z, zst[2], acc);
        acc = fmaf(w0.w, zst[3], acc);
        acc = fmaf(w1.x, zst[4], acc);
        acc = fmaf(w1.y, zst[5], acc);
        acc = fmaf(w1.z, zst[6], acc);
        acc = fmaf(w1.w, zst[7], acc);
        acc += obs[ol];
        op[(size_t)ol * T_] = acc;
    }
}

// ---------------------------------------------------------------------------
__global__ void kloss(float* __restrict__ out)
{
    int b = threadIdx.x;
    if (b < B_) {
        float m = g_losssum[b] / (float)(DCB * T_);
        out[OUT_COMMIT + b] = m * 0.005f;
        out[OUT_CBL + b]    = m * 1.0f;
    }
}

// ---------------------------------------------------------------------------
extern "C" void kernel_launch(void* const* d_in, const int* in_sizes, int n_in,
                              void* d_out, int out_size)
{
    const float* z        = (const float*)d_in[0];
    const float* in_v     = (const float*)d_in[1];
    const float* in_g     = (const float*)d_in[2];
    const float* in_b     = (const float*)d_in[3];
    const float* out_v    = (const float*)d_in[4];
    const float* out_g    = (const float*)d_in[5];
    const float* out_b    = (const float*)d_in[6];
    const float* codebook = (const float*)d_in[7];
    float* out = (float*)d_out;

    kprep<<<34, 256>>>(in_v, in_g, out_v, out_g, codebook);
    kinproj<<<dim3(T_/128, B_, DSPLIT), 128>>>(z);
    kcombine<<<NT/256, 256>>>(in_b, out);
    kargmin<<<NT/128, 256>>>(codebook, out);
    koutproj<<<dim3(T_/128, B_, 8), 128>>>(codebook, out_b, out);
    kloss<<<1, 32>>>(out);
}

// round 3
// speedup vs baseline: 3.4506x; 1.1253x over previous
#include <cuda_runtime.h>
#include <cuda_bf16.h>
#include <math.h>

// Problem constants
#define B_    8
#define DIN   1024
#define T_    2048
#define K_    8192
#define DCB   8
#define NT    (B_*T_)          // 16384 total time positions
#define DSPLIT 16
#define DCHUNK (DIN/DSPLIT)    // 64
#define KSPLIT 4
#define KP    (K_/KSPLIT)      // 2048 codes per partition

// Output layout (flattened tuple, all float32):
// z_q_out [B,1024,T] | commit[B] | cb_loss[B] | indices[B,T] | z_e[B,8,T]
#define OUT_ZQ     0
#define OUT_COMMIT (B_*DIN*T_)
#define OUT_CBL    (OUT_COMMIT + B_)
#define OUT_IDX    (OUT_CBL + B_)
#define OUT_ZE     (OUT_IDX + NT)

// Scratch (device globals; no allocation allowed)
__device__ float g_w_in[DCB*DIN];                    // normalized in weights [c][d]
__device__ float g_w_out[DIN*DCB];                   // normalized out weights [o][c]
__device__ __align__(16) float g_cbn[K_*DCB];        // normalized codebook
__device__ __align__(16) unsigned long long g_sc2[K_]; // packed (-0.5*||cn||^2, 0)
__device__ __align__(16) float g_encn[NT*DCB];       // normalized encodings
__device__ __align__(16) float g_part[DSPLIT*NT*DCB];// split-K partials (8MB)
__device__ float g_cands[KSPLIT*NT];                 // per-partition best score
__device__ int   g_candi[KSPLIT*NT];                 // per-partition best index
__device__ int   g_idx[NT];                          // final argmin indices
__device__ float g_losssum[B_];                      // per-batch sum of (z_e-z_q)^2

// ---- packed f32x2 helpers ----
__device__ __forceinline__ unsigned long long fma2(unsigned long long a,
                                                   unsigned long long b,
                                                   unsigned long long c) {
    unsigned long long d;
    asm("fma.rn.f32x2 %0, %1, %2, %3;" : "=l"(d) : "l"(a), "l"(b), "l"(c));
    return d;
}
__device__ __forceinline__ unsigned long long mul2(unsigned long long a,
                                                   unsigned long long b) {
    unsigned long long d;
    asm("mul.rn.f32x2 %0, %1, %2;" : "=l"(d) : "l"(a), "l"(b));
    return d;
}
__device__ __forceinline__ void unpk2(unsigned long long p, float& lo, float& hi) {
    asm("mov.b64 {%0, %1}, %2;" : "=f"(lo), "=f"(hi) : "l"(p));
}

// ---------------------------------------------------------------------------
// Kernel W: prep — normalize codebook (+ packed -sc/2), w_out, w_in.
// ---------------------------------------------------------------------------
__global__ void kprep(const float* __restrict__ in_v,
                      const float* __restrict__ in_g,
                      const float* __restrict__ out_v,
                      const float* __restrict__ out_g,
                      const float* __restrict__ codebook)
{
    int bid = blockIdx.x;
    int tid = threadIdx.x;

    if (bid < 32) {
        int row = bid * 256 + tid;             // 0..8191
        const float4* c4 = (const float4*)codebook + row * 2;
        float4 a = c4[0], b = c4[1];
        float ss = a.x*a.x + a.y*a.y + a.z*a.z + a.w*a.w
                 + b.x*b.x + b.y*b.y + b.z*b.z + b.w*b.w;
        float nm = fmaxf(sqrtf(ss), 1e-12f);
        float inv = 1.0f / nm;
        float4 na = make_float4(a.x*inv, a.y*inv, a.z*inv, a.w*inv);
        float4 nb = make_float4(b.x*inv, b.y*inv, b.z*inv, b.w*inv);
        float4* o4 = (float4*)g_cbn + row * 2;
        o4[0] = na; o4[1] = nb;
        float sc = na.x*na.x + na.y*na.y + na.z*na.z + na.w*na.w
                 + nb.x*nb.x + nb.y*nb.y + nb.z*nb.z + nb.w*nb.w;
        g_sc2[row] = (unsigned long long)__float_as_uint(-0.5f * sc); // hi = 0
    } else if (bid == 32) {
        for (int o = tid; o < DIN; o += 256) {
            const float4* v4 = (const float4*)out_v + o * 2;
            float4 a = v4[0], b = v4[1];
            float ss = a.x*a.x + a.y*a.y + a.z*a.z + a.w*a.w
                     + b.x*b.x + b.y*b.y + b.z*b.z + b.w*b.w;
            float s = out_g[o] / sqrtf(ss);
            float4* w4 = (float4*)g_w_out + o * 2;
            w4[0] = make_float4(a.x*s, a.y*s, a.z*s, a.w*s);
            w4[1] = make_float4(b.x*s, b.y*s, b.z*s, b.w*s);
        }
    } else {
        __shared__ float norms[DCB];
        int w = tid >> 5, l = tid & 31;
        if (w < DCB) {
            float ss = 0.f;
            const float* vr = in_v + w * DIN;
            for (int j = l; j < DIN; j += 32) { float x = vr[j]; ss = fmaf(x, x, ss); }
            #pragma unroll
            for (int off = 16; off; off >>= 1)
                ss += __shfl_xor_sync(0xffffffffu, ss, off);
            if (l == 0) norms[w] = sqrtf(ss);
        }
        __syncthreads();
        for (int flat = tid; flat < DCB*DIN; flat += 256) {
            int c = flat >> 10;
            g_w_in[flat] = in_g[c] * in_v[flat] / norms[c];
        }
        if (tid < B_) g_losssum[tid] = 0.f;
    }
}

// ---------------------------------------------------------------------------
// Kernel A1: split-K in-projection partials.
// ---------------------------------------------------------------------------
__global__ void kinproj(const float* __restrict__ z)
{
    __shared__ __align__(16) float wst[DCHUNK * DCB];   // transposed [j][c], 2KB
    int tid = threadIdx.x;
    int ds  = blockIdx.z;

    for (int e = tid; e < DCHUNK*DCB; e += 128) {
        int c = e >> 6;
        int j = e & (DCHUNK-1);
        wst[j*DCB + c] = g_w_in[c*DIN + ds*DCHUNK + j];
    }
    __syncthreads();

    int t = blockIdx.x * 128 + tid;
    int b = blockIdx.y;
    const float* zp = z + ((size_t)b * DIN + ds * DCHUNK) * T_ + t;

    float acc[DCB];
    #pragma unroll
    for (int c = 0; c < DCB; c++) acc[c] = 0.f;

    const float4* w4 = (const float4*)wst;
    #pragma unroll 8
    for (int j = 0; j < DCHUNK; j++) {
        float zv = zp[(size_t)j * T_];
        float4 w0 = w4[j*2];
        float4 w1 = w4[j*2 + 1];
        acc[0] = fmaf(w0.x, zv, acc[0]);
        acc[1] = fmaf(w0.y, zv, acc[1]);
        acc[2] = fmaf(w0.z, zv, acc[2]);
        acc[3] = fmaf(w0.w, zv, acc[3]);
        acc[4] = fmaf(w1.x, zv, acc[4]);
        acc[5] = fmaf(w1.y, zv, acc[5]);
        acc[6] = fmaf(w1.z, zv, acc[6]);
        acc[7] = fmaf(w1.w, zv, acc[7]);
    }

    int tg = b * T_ + t;
    float4* p4 = (float4*)(g_part + ((size_t)ds * NT + tg) * DCB);
    p4[0] = make_float4(acc[0], acc[1], acc[2], acc[3]);
    p4[1] = make_float4(acc[4], acc[5], acc[6], acc[7]);
}

// ---------------------------------------------------------------------------
// Kernel A2: combine partials, add bias, write z_e, write normalized enc.
// ---------------------------------------------------------------------------
__global__ void kcombine(const float* __restrict__ in_b,
                         float* __restrict__ out)
{
    int tg = blockIdx.x * 256 + threadIdx.x;
    int b = tg >> 11;
    int t = tg & (T_-1);

    float4 a0 = make_float4(0,0,0,0), a1 = make_float4(0,0,0,0);
    #pragma unroll
    for (int ds = 0; ds < DSPLIT; ds++) {
        const float4* p4 = (const float4*)(g_part + ((size_t)ds * NT + tg) * DCB);
        float4 q0 = p4[0], q1 = p4[1];
        a0.x += q0.x; a0.y += q0.y; a0.z += q0.z; a0.w += q0.w;
        a1.x += q1.x; a1.y += q1.y; a1.z += q1.z; a1.w += q1.w;
    }
    float ze[DCB] = { a0.x + in_b[0], a0.y + in_b[1], a0.z + in_b[2], a0.w + in_b[3],
                      a1.x + in_b[4], a1.y + in_b[5], a1.z + in_b[6], a1.w + in_b[7] };

    float* oz = out + OUT_ZE + (size_t)b * DCB * T_ + t;
    float ss = 0.f;
    #pragma unroll
    for (int c = 0; c < DCB; c++) {
        oz[(size_t)c * T_] = ze[c];
        ss = fmaf(ze[c], ze[c], ss);
    }
    float inv = 1.0f / fmaxf(sqrtf(ss), 1e-12f);
    float4* en4 = (float4*)g_encn + (size_t)tg * 2;
    en4[0] = make_float4(ze[0]*inv, ze[1]*inv, ze[2]*inv, ze[3]*inv);
    en4[1] = make_float4(ze[4]*inv, ze[5]*inv, ze[6]*inv, ze[7]*inv);
}

// ---------------------------------------------------------------------------
// Kernel B: K-partitioned argmax of score = dot(enc_n, cb_n) - sc/2.
// grid (NT/128, KSPLIT), 256 threads. Each 8-lane group serves 4 queries.
// Emits per-partition (best score, best index) candidates.
// ---------------------------------------------------------------------------
#define TILE_K 1024
#define QB 4
__global__ void __launch_bounds__(256) kargmin(float* __restrict__ out)
{
    __shared__ __align__(16) float cbs[TILE_K * DCB];           // 32KB
    __shared__ __align__(16) unsigned long long scs2[TILE_K];   // 8KB

    int tid = threadIdx.x;
    int r = tid & 7;
    int g = tid >> 3;
    int q0 = blockIdx.x * 128 + g * QB;
    int kp0 = blockIdx.y * KP;

    // load 4 query encodings as packed f32x2
    unsigned long long e01[QB], e23[QB], e45[QB], e67[QB];
    #pragma unroll
    for (int q = 0; q < QB; q++) {
        const ulonglong2* e2 = (const ulonglong2*)g_encn + (size_t)(q0 + q) * 2;
        ulonglong2 A = e2[0], Bv = e2[1];
        e01[q] = A.x; e23[q] = A.y; e45[q] = Bv.x; e67[q] = Bv.y;
    }

    float best[QB]; int bi[QB];
    #pragma unroll
    for (int q = 0; q < QB; q++) { best[q] = -3.4e38f; bi[q] = 0; }

    const ulonglong2* c2 = (const ulonglong2*)cbs;

    for (int kb = kp0; kb < kp0 + KP; kb += TILE_K) {
        __syncthreads();
        {
            const float4* g4 = (const float4*)g_cbn + (size_t)kb * 2;
            float4* d4 = (float4*)cbs;
            #pragma unroll
            for (int j = tid; j < TILE_K*DCB/4; j += 256) d4[j] = g4[j];
            const ulonglong2* s2g = (const ulonglong2*)(g_sc2 + kb);
            ulonglong2* s2s = (ulonglong2*)scs2;
            #pragma unroll
            for (int j = tid; j < TILE_K/2; j += 256) s2s[j] = s2g[j];
        }
        __syncthreads();

        #pragma unroll 4
        for (int i = 0; i < TILE_K/8; i++) {
            int kl = i*8 + r;
            ulonglong2 ca = c2[kl*2];
            ulonglong2 cb = c2[kl*2 + 1];
            unsigned long long s2 = scs2[kl];
            #pragma unroll
            for (int q = 0; q < QB; q++) {
                unsigned long long p = fma2(e01[q], ca.x, fma2(e23[q], ca.y,
                                         fma2(e45[q], cb.x, fma2(e67[q], cb.y, s2))));
                float lo, hi; unpk2(p, lo, hi);
                float v = lo + hi;                    // dot - sc/2 (maximize)
                if (v > best[q]) { best[q] = v; bi[q] = kb + kl; }
            }
        }
    }

    // reduce across the 8 lanes (max score; lowest index on tie)
    #pragma unroll
    for (int q = 0; q < QB; q++) {
        #pragma unroll
        for (int off = 4; off; off >>= 1) {
            float ov = __shfl_xor_sync(0xffffffffu, best[q], off);
            int   oi = __shfl_xor_sync(0xffffffffu, bi[q],   off);
            if (ov > best[q] || (ov == best[q] && oi < bi[q])) { best[q] = ov; bi[q] = oi; }
        }
    }

    if (r == 0) {
        #pragma unroll
        for (int q = 0; q < QB; q++) {
            g_cands[blockIdx.y * NT + q0 + q] = best[q];
            g_candi[blockIdx.y * NT + q0 + q] = bi[q];
        }
    }
}

// ---------------------------------------------------------------------------
// Kernel B2: merge per-partition candidates, write indices, compute loss sums.
// grid NT/256, 256 threads; each block spans one batch's queries.
// ---------------------------------------------------------------------------
__global__ void kreduce(const float* __restrict__ codebook,
                        float* __restrict__ out)
{
    __shared__ float sloss;
    int tid = threadIdx.x;
    int q = blockIdx.x * 256 + tid;
    int b = q >> 11;
    int t = q & (T_-1);

    if (tid == 0) sloss = 0.f;
    __syncthreads();

    float best = -3.4e38f; int bi = 0;
    #pragma unroll
    for (int p = 0; p < KSPLIT; p++) {
        float v = g_cands[p * NT + q];
        int   i = g_candi[p * NT + q];
        if (v > best || (v == best && i < bi)) { best = v; bi = i; }
    }
    g_idx[q] = bi;
    out[OUT_IDX + q] = (float)bi;

    // loss: sum over 8 dims of (z_e - codebook[bi])^2
    const float4* q4 = (const float4*)codebook + (size_t)bi * 2;
    float4 qa = q4[0], qb = q4[1];
    float zq[DCB] = {qa.x, qa.y, qa.z, qa.w, qb.x, qb.y, qb.z, qb.w};
    float s = 0.f;
    #pragma unroll
    for (int c = 0; c < DCB; c++) {
        float ze = out[OUT_ZE + ((size_t)b * DCB + c) * T_ + t];
        float d = ze - zq[c];
        s = fmaf(d, d, s);
    }
    #pragma unroll
    for (int off = 16; off; off >>= 1)
        s += __shfl_xor_sync(0xffffffffu, s, off);
    if ((tid & 31) == 0) atomicAdd(&sloss, s);

    __syncthreads();
    if (tid == 0) atomicAdd(&g_losssum[b], sloss);
}

// ---------------------------------------------------------------------------
// Kernel C: out-projection, o split into 16 chunks of 64, 256 threads.
// ---------------------------------------------------------------------------
#define OCH 64
__global__ void koutproj(const float* __restrict__ codebook,
                         const float* __restrict__ out_b,
                         float* __restrict__ out)
{
    __shared__ __align__(16) float ws[OCH * DCB];   // 2KB
    __shared__ float obs[OCH];

    int tid = threadIdx.x;
    int t = blockIdx.x * 256 + tid;
    int b = blockIdx.y;
    int obase = blockIdx.z * OCH;

    {
        const float4* s4 = (const float4*)(g_w_out + obase * DCB);
        float4* d4 = (float4*)ws;
        if (tid < OCH*DCB/4) d4[tid] = s4[tid];
        if (tid >= 128 && tid < 128 + OCH) obs[tid - 128] = out_b[obase + tid - 128];
    }

    int ki = g_idx[b * T_ + t];
    const float4* q4 = (const float4*)codebook + (size_t)ki * 2;
    float4 qa = q4[0], qb = q4[1];
    float zq[DCB] = {qa.x, qa.y, qa.z, qa.w, qb.x, qb.y, qb.z, qb.w};
    float zst[DCB];
    #pragma unroll
    for (int c = 0; c < DCB; c++) {
        float ze = out[OUT_ZE + ((size_t)b * DCB + c) * T_ + t];
        zst[c] = ze + (zq[c] - ze);   // straight-through forward value
    }
    __syncthreads();

    const float4* ws4 = (const float4*)ws;
    float* op = out + OUT_ZQ + ((size_t)b * DIN + obase) * T_ + t;

    #pragma unroll 8
    for (int ol = 0; ol < OCH; ol++) {
        float4 w0 = ws4[ol*2];
        float4 w1 = ws4[ol*2 + 1];
        float acc = w0.x * zst[0];
        acc = fmaf(w0.y, zst[1], acc);
        acc = fmaf(w0.z, zst[2], acc);
        acc = fmaf(w0.w, zst[3], acc);
        acc = fmaf(w1.x, zst[4], acc);
        acc = fmaf(w1.y, zst[5], acc);
        acc = fmaf(w1.z, zst[6], acc);
        acc = fmaf(w1.w, zst[7], acc);
        acc += obs[ol];
        op[(size_t)ol * T_] = acc;
    }
}

// ---------------------------------------------------------------------------
__global__ void kloss(float* __restrict__ out)
{
    int b = threadIdx.x;
    if (b < B_) {
        float m = g_losssum[b] / (float)(DCB * T_);
        out[OUT_COMMIT + b] = m * 0.005f;
        out[OUT_CBL + b]    = m * 1.0f;
    }
}

// ---------------------------------------------------------------------------
extern "C" void kernel_launch(void* const* d_in, const int* in_sizes, int n_in,
                              void* d_out, int out_size)
{
    const float* z        = (const float*)d_in[0];
    const float* in_v     = (const float*)d_in[1];
    const float* in_g     = (const float*)d_in[2];
    const float* in_b     = (const float*)d_in[3];
    const float* out_v    = (const float*)d_in[4];
    const float* out_g    = (const float*)d_in[5];
    const float* out_b    = (const float*)d_in[6];
    const float* codebook = (const float*)d_in[7];
    float* out = (float*)d_out;

    kprep<<<34, 256>>>(in_v, in_g, out_v, out_g, codebook);
    kinproj<<<dim3(T_/128, B_, DSPLIT), 128>>>(z);
    kcombine<<<NT/256, 256>>>(in_b, out);
    kargmin<<<dim3(NT/128, KSPLIT), 256>>>(out);
    kreduce<<<NT/256, 256>>>(codebook, out);
    koutproj<<<dim3(T_/256, B_, DIN/OCH), 256>>>(codebook, out_b, out);
    kloss<<<1, 32>>>(out);
}

// round 4
// speedup vs baseline: 3.9156x; 1.1348x over previous
#include <cuda_runtime.h>
#include <cuda_bf16.h>
#include <math.h>

// Problem constants
#define B_    8
#define DIN   1024
#define T_    2048
#define K_    8192
#define DCB   8
#define NT    (B_*T_)          // 16384 total time positions
#define DSPLIT 16
#define DCHUNK (DIN/DSPLIT)    // 64
#define KSPLIT 8
#define KP    (K_/KSPLIT)      // 1024 codes per partition

// Output layout (flattened tuple, all float32):
// z_q_out [B,1024,T] | commit[B] | cb_loss[B] | indices[B,T] | z_e[B,8,T]
#define OUT_ZQ     0
#define OUT_COMMIT (B_*DIN*T_)
#define OUT_CBL    (OUT_COMMIT + B_)
#define OUT_IDX    (OUT_CBL + B_)
#define OUT_ZE     (OUT_IDX + NT)

// Scratch (device globals; no allocation allowed)
__device__ float g_w_in[DCB*DIN];                    // normalized in weights [c][d]
__device__ float g_w_out[DIN*DCB];                   // normalized out weights [o][c]
__device__ __align__(16) float g_cbn[K_*DCB];        // normalized codebook
__device__ __align__(16) unsigned long long g_sc2[K_]; // packed (-0.5*||cn||^2, 0)
__device__ __align__(16) float g_encn[NT*DCB];       // normalized encodings
__device__ __align__(16) float g_part[DSPLIT*NT*DCB];// split-K partials (8MB)
__device__ float g_cands[KSPLIT*NT];                 // per-partition best score
__device__ int   g_candi[KSPLIT*NT];                 // per-partition best index
__device__ int   g_idx[NT];                          // final argmin indices
__device__ float g_losssum[B_];                      // per-batch sum of (z_e-z_q)^2

// ---- packed f32x2 helpers ----
__device__ __forceinline__ unsigned long long fma2(unsigned long long a,
                                                   unsigned long long b,
                                                   unsigned long long c) {
    unsigned long long d;
    asm("fma.rn.f32x2 %0, %1, %2, %3;" : "=l"(d) : "l"(a), "l"(b), "l"(c));
    return d;
}
__device__ __forceinline__ void unpk2(unsigned long long p, float& lo, float& hi) {
    asm("mov.b64 {%0, %1}, %2;" : "=f"(lo), "=f"(hi) : "l"(p));
}

// ---------------------------------------------------------------------------
// Kernel W: prep — normalize codebook (+ packed -sc/2), w_out, w_in.
// ---------------------------------------------------------------------------
__global__ void kprep(const float* __restrict__ in_v,
                      const float* __restrict__ in_g,
                      const float* __restrict__ out_v,
                      const float* __restrict__ out_g,
                      const float* __restrict__ codebook)
{
    int bid = blockIdx.x;
    int tid = threadIdx.x;

    if (bid < 32) {
        int row = bid * 256 + tid;             // 0..8191
        const float4* c4 = (const float4*)codebook + row * 2;
        float4 a = c4[0], b = c4[1];
        float ss = a.x*a.x + a.y*a.y + a.z*a.z + a.w*a.w
                 + b.x*b.x + b.y*b.y + b.z*b.z + b.w*b.w;
        float nm = fmaxf(sqrtf(ss), 1e-12f);
        float inv = 1.0f / nm;
        float4 na = make_float4(a.x*inv, a.y*inv, a.z*inv, a.w*inv);
        float4 nb = make_float4(b.x*inv, b.y*inv, b.z*inv, b.w*inv);
        float4* o4 = (float4*)g_cbn + row * 2;
        o4[0] = na; o4[1] = nb;
        float sc = na.x*na.x + na.y*na.y + na.z*na.z + na.w*na.w
                 + nb.x*nb.x + nb.y*nb.y + nb.z*nb.z + nb.w*nb.w;
        g_sc2[row] = (unsigned long long)__float_as_uint(-0.5f * sc); // hi = 0
    } else if (bid == 32) {
        for (int o = tid; o < DIN; o += 256) {
            const float4* v4 = (const float4*)out_v + o * 2;
            float4 a = v4[0], b = v4[1];
            float ss = a.x*a.x + a.y*a.y + a.z*a.z + a.w*a.w
                     + b.x*b.x + b.y*b.y + b.z*b.z + b.w*b.w;
            float s = out_g[o] / sqrtf(ss);
            float4* w4 = (float4*)g_w_out + o * 2;
            w4[0] = make_float4(a.x*s, a.y*s, a.z*s, a.w*s);
            w4[1] = make_float4(b.x*s, b.y*s, b.z*s, b.w*s);
        }
    } else {
        __shared__ float norms[DCB];
        int w = tid >> 5, l = tid & 31;
        if (w < DCB) {
            float ss = 0.f;
            const float* vr = in_v + w * DIN;
            for (int j = l; j < DIN; j += 32) { float x = vr[j]; ss = fmaf(x, x, ss); }
            #pragma unroll
            for (int off = 16; off; off >>= 1)
                ss += __shfl_xor_sync(0xffffffffu, ss, off);
            if (l == 0) norms[w] = sqrtf(ss);
        }
        __syncthreads();
        for (int flat = tid; flat < DCB*DIN; flat += 256) {
            int c = flat >> 10;
            g_w_in[flat] = in_g[c] * in_v[flat] / norms[c];
        }
        if (tid < B_) g_losssum[tid] = 0.f;
    }
}

// ---------------------------------------------------------------------------
// Kernel A1: split-K in-projection partials.
// ---------------------------------------------------------------------------
__global__ void kinproj(const float* __restrict__ z)
{
    __shared__ __align__(16) float wst[DCHUNK * DCB];   // transposed [j][c], 2KB
    int tid = threadIdx.x;
    int ds  = blockIdx.z;

    for (int e = tid; e < DCHUNK*DCB; e += 128) {
        int c = e >> 6;
        int j = e & (DCHUNK-1);
        wst[j*DCB + c] = g_w_in[c*DIN + ds*DCHUNK + j];
    }
    __syncthreads();

    int t = blockIdx.x * 128 + tid;
    int b = blockIdx.y;
    const float* zp = z + ((size_t)b * DIN + ds * DCHUNK) * T_ + t;

    float acc[DCB];
    #pragma unroll
    for (int c = 0; c < DCB; c++) acc[c] = 0.f;

    const float4* w4 = (const float4*)wst;
    #pragma unroll 8
    for (int j = 0; j < DCHUNK; j++) {
        float zv = zp[(size_t)j * T_];
        float4 w0 = w4[j*2];
        float4 w1 = w4[j*2 + 1];
        acc[0] = fmaf(w0.x, zv, acc[0]);
        acc[1] = fmaf(w0.y, zv, acc[1]);
        acc[2] = fmaf(w0.z, zv, acc[2]);
        acc[3] = fmaf(w0.w, zv, acc[3]);
        acc[4] = fmaf(w1.x, zv, acc[4]);
        acc[5] = fmaf(w1.y, zv, acc[5]);
        acc[6] = fmaf(w1.z, zv, acc[6]);
        acc[7] = fmaf(w1.w, zv, acc[7]);
    }

    int tg = b * T_ + t;
    float4* p4 = (float4*)(g_part + ((size_t)ds * NT + tg) * DCB);
    p4[0] = make_float4(acc[0], acc[1], acc[2], acc[3]);
    p4[1] = make_float4(acc[4], acc[5], acc[6], acc[7]);
}

// ---------------------------------------------------------------------------
// Kernel A2: combine partials, add bias, write z_e, write normalized enc.
// ---------------------------------------------------------------------------
__global__ void kcombine(const float* __restrict__ in_b,
                         float* __restrict__ out)
{
    int tg = blockIdx.x * 256 + threadIdx.x;
    int b = tg >> 11;
    int t = tg & (T_-1);

    float4 a0 = make_float4(0,0,0,0), a1 = make_float4(0,0,0,0);
    #pragma unroll
    for (int ds = 0; ds < DSPLIT; ds++) {
        const float4* p4 = (const float4*)(g_part + ((size_t)ds * NT + tg) * DCB);
        float4 q0 = p4[0], q1 = p4[1];
        a0.x += q0.x; a0.y += q0.y; a0.z += q0.z; a0.w += q0.w;
        a1.x += q1.x; a1.y += q1.y; a1.z += q1.z; a1.w += q1.w;
    }
    float ze[DCB] = { a0.x + in_b[0], a0.y + in_b[1], a0.z + in_b[2], a0.w + in_b[3],
                      a1.x + in_b[4], a1.y + in_b[5], a1.z + in_b[6], a1.w + in_b[7] };

    float* oz = out + OUT_ZE + (size_t)b * DCB * T_ + t;
    float ss = 0.f;
    #pragma unroll
    for (int c = 0; c < DCB; c++) {
        oz[(size_t)c * T_] = ze[c];
        ss = fmaf(ze[c], ze[c], ss);
    }
    float inv = 1.0f / fmaxf(sqrtf(ss), 1e-12f);
    float4* en4 = (float4*)g_encn + (size_t)tg * 2;
    en4[0] = make_float4(ze[0]*inv, ze[1]*inv, ze[2]*inv, ze[3]*inv);
    en4[1] = make_float4(ze[4]*inv, ze[5]*inv, ze[6]*inv, ze[7]*inv);
}

// ---------------------------------------------------------------------------
// Kernel B: K-partitioned argmax of score = dot(enc_n, cb_n) - sc/2.
// 128 threads = 16 groups of 8 lanes; QB=8 queries per group -> 128 q/block.
// grid (NT/128, KSPLIT=8) = 1024 blocks, one 1024-code tile each.
// ---------------------------------------------------------------------------
#define QB 8
__global__ void __launch_bounds__(128) kargmin(float* __restrict__ out)
{
    __shared__ __align__(16) float cbs[KP * DCB];           // 32KB
    __shared__ __align__(16) unsigned long long scs2[KP];   // 8KB

    int tid = threadIdx.x;
    int r = tid & 7;
    int g = tid >> 3;                       // group 0..15
    int q0 = blockIdx.x * 128 + g * QB;
    int kp0 = blockIdx.y * KP;

    // cooperative tile load: 1024 codes (32B each) + 1024 seeds (8B each)
    {
        const float4* g4 = (const float4*)g_cbn + (size_t)kp0 * 2;
        float4* d4 = (float4*)cbs;
        #pragma unroll
        for (int j = tid; j < KP*DCB/4; j += 128) d4[j] = g4[j];
        const ulonglong2* s2g = (const ulonglong2*)(g_sc2 + kp0);
        ulonglong2* s2s = (ulonglong2*)scs2;
        #pragma unroll
        for (int j = tid; j < KP/2; j += 128) s2s[j] = s2g[j];
    }

    // load 8 query encodings as packed f32x2
    unsigned long long e01[QB], e23[QB], e45[QB], e67[QB];
    #pragma unroll
    for (int q = 0; q < QB; q++) {
        const ulonglong2* e2 = (const ulonglong2*)g_encn + (size_t)(q0 + q) * 2;
        ulonglong2 A = e2[0], Bv = e2[1];
        e01[q] = A.x; e23[q] = A.y; e45[q] = Bv.x; e67[q] = Bv.y;
    }

    float best[QB]; int bi[QB];
    #pragma unroll
    for (int q = 0; q < QB; q++) { best[q] = -3.4e38f; bi[q] = 0; }

    __syncthreads();

    const ulonglong2* c2 = (const ulonglong2*)cbs;

    #pragma unroll 4
    for (int i = 0; i < KP/8; i++) {
        int kl = i*8 + r;
        ulonglong2 ca = c2[kl*2];
        ulonglong2 cb = c2[kl*2 + 1];
        unsigned long long s2 = scs2[kl];
        #pragma unroll
        for (int q = 0; q < QB; q++) {
            unsigned long long p = fma2(e01[q], ca.x, fma2(e23[q], ca.y,
                                     fma2(e45[q], cb.x, fma2(e67[q], cb.y, s2))));
            float lo, hi; unpk2(p, lo, hi);
            float v = lo + hi;                    // dot - sc/2 (maximize)
            if (v > best[q]) { best[q] = v; bi[q] = kl; }
        }
    }

    // reduce across the 8 lanes (max score; lowest index on tie)
    #pragma unroll
    for (int q = 0; q < QB; q++) {
        #pragma unroll
        for (int off = 4; off; off >>= 1) {
            float ov = __shfl_xor_sync(0xffffffffu, best[q], off);
            int   oi = __shfl_xor_sync(0xffffffffu, bi[q],   off);
            if (ov > best[q] || (ov == best[q] && oi < bi[q])) { best[q] = ov; bi[q] = oi; }
        }
    }

    if (r == 0) {
        #pragma unroll
        for (int q = 0; q < QB; q++) {
            g_cands[blockIdx.y * NT + q0 + q] = best[q];
            g_candi[blockIdx.y * NT + q0 + q] = kp0 + bi[q];
        }
    }
}

// ---------------------------------------------------------------------------
// Kernel B2: merge per-partition candidates, write indices, compute loss sums.
// ---------------------------------------------------------------------------
__global__ void kreduce(const float* __restrict__ codebook,
                        float* __restrict__ out)
{
    __shared__ float sloss;
    int tid = threadIdx.x;
    int q = blockIdx.x * 256 + tid;
    int b = q >> 11;
    int t = q & (T_-1);

    if (tid == 0) sloss = 0.f;
    __syncthreads();

    float best = -3.4e38f; int bi = 0;
    #pragma unroll
    for (int p = 0; p < KSPLIT; p++) {
        float v = g_cands[p * NT + q];
        int   i = g_candi[p * NT + q];
        if (v > best || (v == best && i < bi)) { best = v; bi = i; }
    }
    g_idx[q] = bi;
    out[OUT_IDX + q] = (float)bi;

    // loss: sum over 8 dims of (z_e - codebook[bi])^2
    const float4* q4 = (const float4*)codebook + (size_t)bi * 2;
    float4 qa = q4[0], qb = q4[1];
    float zq[DCB] = {qa.x, qa.y, qa.z, qa.w, qb.x, qb.y, qb.z, qb.w};
    float s = 0.f;
    #pragma unroll
    for (int c = 0; c < DCB; c++) {
        float ze = out[OUT_ZE + ((size_t)b * DCB + c) * T_ + t];
        float d = ze - zq[c];
        s = fmaf(d, d, s);
    }
    #pragma unroll
    for (int off = 16; off; off >>= 1)
        s += __shfl_xor_sync(0xffffffffu, s, off);
    if ((tid & 31) == 0) atomicAdd(&sloss, s);

    __syncthreads();
    if (tid == 0) atomicAdd(&g_losssum[b], sloss);
}

// ---------------------------------------------------------------------------
// Kernel C: out-projection, o split into 16 chunks of 64, 256 threads.
// ---------------------------------------------------------------------------
#define OCH 64
__global__ void koutproj(const float* __restrict__ codebook,
                         const float* __restrict__ out_b,
                         float* __restrict__ out)
{
    __shared__ __align__(16) float ws[OCH * DCB];   // 2KB
    __shared__ float obs[OCH];

    int tid = threadIdx.x;
    int t = blockIdx.x * 256 + tid;
    int b = blockIdx.y;
    int obase = blockIdx.z * OCH;

    {
        const float4* s4 = (const float4*)(g_w_out + obase * DCB);
        float4* d4 = (float4*)ws;
        if (tid < OCH*DCB/4) d4[tid] = s4[tid];
        if (tid >= 128 && tid < 128 + OCH) obs[tid - 128] = out_b[obase + tid - 128];
    }

    int ki = g_idx[b * T_ + t];
    const float4* q4 = (const float4*)codebook + (size_t)ki * 2;
    float4 qa = q4[0], qb = q4[1];
    float zq[DCB] = {qa.x, qa.y, qa.z, qa.w, qb.x, qb.y, qb.z, qb.w};
    float zst[DCB];
    #pragma unroll
    for (int c = 0; c < DCB; c++) {
        float ze = out[OUT_ZE + ((size_t)b * DCB + c) * T_ + t];
        zst[c] = ze + (zq[c] - ze);   // straight-through forward value
    }
    __syncthreads();

    const float4* ws4 = (const float4*)ws;
    float* op = out + OUT_ZQ + ((size_t)b * DIN + obase) * T_ + t;

    #pragma unroll 8
    for (int ol = 0; ol < OCH; ol++) {
        float4 w0 = ws4[ol*2];
        float4 w1 = ws4[ol*2 + 1];
        float acc = w0.x * zst[0];
        acc = fmaf(w0.y, zst[1], acc);
        acc = fmaf(w0.z, zst[2], acc);
        acc = fmaf(w0.w, zst[3], acc);
        acc = fmaf(w1.x, zst[4], acc);
        acc = fmaf(w1.y, zst[5], acc);
        acc = fmaf(w1.z, zst[6], acc);
        acc = fmaf(w1.w, zst[7], acc);
        acc += obs[ol];
        op[(size_t)ol * T_] = acc;
    }
}

// ---------------------------------------------------------------------------
__global__ void kloss(float* __restrict__ out)
{
    int b = threadIdx.x;
    if (b < B_) {
        float m = g_losssum[b] / (float)(DCB * T_);
        out[OUT_COMMIT + b] = m * 0.005f;
        out[OUT_CBL + b]    = m * 1.0f;
    }
}

// ---------------------------------------------------------------------------
extern "C" void kernel_launch(void* const* d_in, const int* in_sizes, int n_in,
                              void* d_out, int out_size)
{
    const float* z        = (const float*)d_in[0];
    const float* in_v     = (const float*)d_in[1];
    const float* in_g     = (const float*)d_in[2];
    const float* in_b     = (const float*)d_in[3];
    const float* out_v    = (const float*)d_in[4];
    const float* out_g    = (const float*)d_in[5];
    const float* out_b    = (const float*)d_in[6];
    const float* codebook = (const float*)d_in[7];
    float* out = (float*)d_out;

    kprep<<<34, 256>>>(in_v, in_g, out_v, out_g, codebook);
    kinproj<<<dim3(T_/128, B_, DSPLIT), 128>>>(z);
    kcombine<<<NT/256, 256>>>(in_b, out);
    kargmin<<<dim3(NT/128, KSPLIT), 128>>>(out);
    kreduce<<<NT/256, 256>>>(codebook, out);
    koutproj<<<dim3(T_/256, B_, DIN/OCH), 256>>>(codebook, out_b, out);
    kloss<<<1, 32>>>(out);
}